// round 16
// baseline (speedup 1.0000x reference)
#include <cuda_runtime.h>

// ---------------------------------------------------------------------------
// MaskRemoval — R16: single kernel, SINGLE-PASS final write.
//   grid (1D), dispatch order:
//     [0, N*NSPLIT)      raster slices -> g_bits + g_msumP + g_rdone++
//     [+, +NCLS)         scan CTAs (spin on rasters; suppression in global
//                        class mask; last ticket compacts -> g_po/g_nk +
//                        keep_inds, resets raster counters, raises g_sdone)
//     [+, +N*WPS)        writer CTAs: spin on g_sdone, then write their
//                        50-row slab of one slot ONCE: zeros outside the
//                        kept box, bilinear inside (no separate zero pass).
// ---------------------------------------------------------------------------

#define MAXN   128
#define NCLS   80
#define MM     28
#define IMG_H  800
#define IMG_W  800
#define W4     (IMG_W / 4)             // 200 float4 per row
#define WPR    25
#define BOXMAX 384
#define NSPLIT 8                       // raster y-slices per ROI
#define WPS    16                      // writer CTAs per slot (50 rows each)
#define BITSW  8192

__device__ int g_keep[MAXN];
__device__ int g_msumP[MAXN][NSPLIT];
__device__ unsigned int g_bits[MAXN][BITSW];
__device__ unsigned int g_cmask[NCLS][IMG_H * WPR];
__device__ int g_rdone[MAXN];
__device__ int g_done  = 0;            // scan ticket
__device__ int g_sdone = 0;            // scan+compaction complete
__device__ int g_wdone = 0;            // writer ticket
__device__ int g_po[MAXN];
__device__ int g_nk;

__device__ __forceinline__ float bilin_ref(const float* lg, float sx, float sy) {
    int ix0 = (int)sx;
    int iy0 = (int)sy;
    int ix1 = min(ix0 + 1, MM - 1);
    int iy1 = min(iy0 + 1, MM - 1);
    float fx = sx - (float)ix0;
    float fy = sy - (float)iy0;
    float v00 = lg[iy0 * MM + ix0], v01 = lg[iy0 * MM + ix1];
    float v10 = lg[iy1 * MM + ix0], v11 = lg[iy1 * MM + ix1];
    return (1.0f - fy) * ((1.0f - fx) * v00 + fx * v01)
         +         fy  * ((1.0f - fx) * v10 + fx * v11);
}

// ---------------------------------------------------------------------------
__global__ __launch_bounds__(256) void k_all(const float* __restrict__ rois,
                                             const float* __restrict__ prob,
                                             const int*   __restrict__ clsidx,
                                             const float* __restrict__ mask_prob,
                                             float* __restrict__ out_keep,
                                             float4* __restrict__ energy4,
                                             int N, int has_keep) {
    __shared__ float sp[MAXN];
    __shared__ int   sord[MAXN];
    __shared__ int   scls[MAXN];
    __shared__ int   s_list[MAXN];
    __shared__ int   pf[MAXN];
    __shared__ int   s_k, s_ticket;
    __shared__ int   s_gx0[16], s_gx1[16], s_gy0[16], s_gy1[16];
    __shared__ int   s_ext[4];
    __shared__ int   s_ovl, s_keep, s_cnt;
    __shared__ float lg[MM * MM];
    __shared__ float2 s_cx[BOXMAX];

    int t = threadIdx.x;
    int warpi = t >> 5;
    int lane  = t & 31;
    int nwarps = blockDim.x >> 5;
    int bid = blockIdx.x;

    const int RCNT  = N * NSPLIT;
    const int SBASE = RCNT;
    const int WBASE = RCNT + NCLS;

    // =========================== WRITER CTAs (tail) ==========================
    if (bid >= WBASE) {
        int wid  = bid - WBASE;
        int slot = wid / WPS;
        int part = wid - slot * WPS;

        if (t == 0) {
            while (atomicAdd(&g_sdone, 0) == 0) __nanosleep(128);
        }
        __syncthreads();
        __threadfence();

        bool kept = (slot < g_nk);
        int x0 = 0, y0 = 0, x1 = 0, y1 = 0;
        int xs0 = 0, xs1 = 0, ys0 = 0, ys1 = 0, bw = 0;
        float scx = 0.f, scy = 0.f;
        bool pre = false;

        if (kept) {
            int o = g_po[slot];
            float4 rb = reinterpret_cast<const float4*>(rois)[o];
            x0 = (int)rb.x; y0 = (int)rb.y; x1 = (int)rb.z; y1 = (int)rb.w;
            xs0 = max(x0, 0); xs1 = min(x1 + 1, IMG_W);
            ys0 = max(y0, 0); ys1 = min(y1 + 1, IMG_H);
            bw = xs1 - xs0;
            if (bw <= 0 || ys1 <= ys0) kept = false;
            if (kept) {
                float wv = fmaxf((float)(x1 - x0 + 1), 1.0f);
                float hv = fmaxf((float)(y1 - y0 + 1), 1.0f);
                scx = 28.0f / wv; scy = 28.0f / hv;
                const float* lp = mask_prob + (long long)o * (MM * MM);
                for (int u = t; u < MM * MM; u += blockDim.x) lg[u] = lp[u];
                pre = (bw <= BOXMAX);
                if (pre) {
                    for (int u = t; u < bw; u += blockDim.x) {
                        float sx = fminf(fmaxf(((float)(xs0 + u) - (float)x0 + 0.5f) * scx - 0.5f, 0.0f), 27.0f);
                        int ix0 = (int)sx;
                        s_cx[u] = make_float2(sx - (float)ix0, __int_as_float(ix0));
                    }
                }
            }
        }
        __syncthreads();

        const int RROWS = IMG_H / WPS;         // 50 rows per writer CTA
        int rbase = part * RROWS;
        float4 z = make_float4(0.f, 0.f, 0.f, 0.f);

        for (int r = warpi; r < RROWS; r += nwarps) {
            int y = rbase + r;
            float4* row4 = energy4 + ((long long)slot * IMG_H + y) * W4;
            bool inband = kept && (y >= ys0) && (y < ys1);

            if (!inband) {                       // pure zero stream
                for (int xq = lane; xq < W4; xq += 32) __stcs(&row4[xq], z);
                continue;
            }

            float sy = fminf(fmaxf(((float)y - (float)y0 + 0.5f) * scy - 0.5f, 0.0f), 27.0f);
            int iy0 = (int)sy;
            int iy1 = min(iy0 + 1, MM - 1);
            float fy = sy - (float)iy0;

            if (pre) {
                int ll = min(lane, MM - 1);
                float r0v = lg[iy0 * MM + ll];
                float r1v = lg[iy1 * MM + ll];
                for (int xq0 = 0; xq0 < W4; xq0 += 32) {
                    int xq = xq0 + lane;
                    bool valid = (xq < W4);
                    float4 v = z;
                    int xb = xq * 4;
                    #pragma unroll
                    for (int l = 0; l < 4; l++) {
                        int x = xb + l;
                        bool in = valid && (x >= xs0) && (x < xs1);
                        float2 cf = s_cx[in ? (x - xs0) : 0];
                        float fx = cf.x;
                        int ix0 = __float_as_int(cf.y);
                        int ix1 = min(ix0 + 1, MM - 1);
                        float v00 = __shfl_sync(0xffffffffu, r0v, ix0);
                        float v01 = __shfl_sync(0xffffffffu, r0v, ix1);
                        float v10 = __shfl_sync(0xffffffffu, r1v, ix0);
                        float v11 = __shfl_sync(0xffffffffu, r1v, ix1);
                        float val = (1.0f - fy) * ((1.0f - fx) * v00 + fx * v01)
                                  +         fy  * ((1.0f - fx) * v10 + fx * v11);
                        if (in) reinterpret_cast<float*>(&v)[l] = val;
                    }
                    if (valid) __stcs(&row4[xq], v);
                }
            } else {                             // huge-box fallback: smem bilinear
                for (int xq = lane; xq < W4; xq += 32) {
                    float4 v = z;
                    int xb = xq * 4;
                    #pragma unroll
                    for (int l = 0; l < 4; l++) {
                        int x = xb + l;
                        if (x >= xs0 && x < xs1) {
                            float sx = fminf(fmaxf(((float)x - (float)x0 + 0.5f) * scx - 0.5f, 0.0f), 27.0f);
                            reinterpret_cast<float*>(&v)[l] = bilin_ref(lg, sx, sy);
                        }
                    }
                    __stcs(&row4[xq], v);
                }
            }
        }

        __syncthreads();
        if (t == 0) {
            int tk = atomicAdd(&g_wdone, 1);
            if (tk == N * WPS - 1) {             // last writer: reset for replay
                g_sdone = 0;
                g_wdone = 0;
                __threadfence();
            }
        }
        return;
    }

    // ============================ RASTER CTAs ================================
    if (bid < RCNT) {
        int i = bid % N;
        int slice = bid / N;

        if (t < N) sp[t] = prob[t];
        __syncthreads();
        if (t < N) {
            float pi = sp[t];
            int r = 0;
            for (int j = 0; j < N; j++) {
                float pj = sp[j];
                r += (pj > pi) || (pj == pi && j < t);
            }
            sord[r] = t;
        }
        if (t == 0) s_cnt = 0;
        __syncthreads();

        int o = sord[i];
        float4 rb = reinterpret_cast<const float4*>(rois)[o];
        int x0 = (int)rb.x, y0 = (int)rb.y, x1 = (int)rb.z, y1 = (int)rb.w;
        int xs0 = max(x0, 0), xs1 = min(x1 + 1, IMG_W);
        int ys0 = max(y0, 0), ys1 = min(y1 + 1, IMG_H);
        int bw = xs1 - xs0, bh = ys1 - ys0;
        bool active = (bw > 0) && (bh > 0);

        float wv = fmaxf((float)(x1 - x0 + 1), 1.0f);
        float hv = fmaxf((float)(y1 - y0 + 1), 1.0f);
        float scx = 28.0f / wv, scy = 28.0f / hv;
        bool pre = active && (bw <= BOXMAX);
        int rows = 0, ry0 = 0;

        if (active) {
            const float* lp = mask_prob + (long long)o * (MM * MM);
            for (int u = t; u < MM * MM; u += blockDim.x) lg[u] = lp[u];
            if (pre) {
                for (int u = t; u < bw; u += blockDim.x) {
                    float sx = fminf(fmaxf(((float)(xs0 + u) - (float)x0 + 0.5f) * scx - 0.5f, 0.0f), 27.0f);
                    int ix0 = (int)sx;
                    s_cx[u] = make_float2(sx - (float)ix0, __int_as_float(ix0));
                }
            }
            int chunk = (bh + NSPLIT - 1) / NSPLIT;
            ry0  = slice * chunk;
            rows = min(chunk, bh - ry0);
        }
        __syncthreads();

        if (active && rows > 0) {
            int xw0 = xs0 >> 5, xw1 = (xs1 + 31) >> 5;
            int nwx = xw1 - xw0;
            bool fits = (nwx * bh <= BITSW);
            int lm = 0;
            for (int r = warpi; r < rows; r += nwarps) {
                int ry = ry0 + r;
                int yy = ys0 + ry;
                float sy = fminf(fmaxf(((float)yy - (float)y0 + 0.5f) * scy - 0.5f, 0.0f), 27.0f);
                int iy0 = (int)sy;
                int iy1 = min(iy0 + 1, MM - 1);
                float fy = sy - (float)iy0;
                int ll = min(lane, MM - 1);
                float r0v = lg[iy0 * MM + ll];
                float r1v = lg[iy1 * MM + ll];
                unsigned int* dst = fits ? &g_bits[i][ry * nwx] : nullptr;
                for (int xw = xw0; xw < xw1; xw++) {
                    int x = (xw << 5) + lane;
                    bool inb = (x >= xs0) && (x < xs1);
                    float val;
                    if (pre) {
                        float2 cf = s_cx[inb ? (x - xs0) : 0];
                        float fx = cf.x;
                        int ix0 = __float_as_int(cf.y);
                        int ix1 = min(ix0 + 1, MM - 1);
                        float v00 = __shfl_sync(0xffffffffu, r0v, ix0);
                        float v01 = __shfl_sync(0xffffffffu, r0v, ix1);
                        float v10 = __shfl_sync(0xffffffffu, r1v, ix0);
                        float v11 = __shfl_sync(0xffffffffu, r1v, ix1);
                        val = (1.0f - fy) * ((1.0f - fx) * v00 + fx * v01)
                            +         fy  * ((1.0f - fx) * v10 + fx * v11);
                    } else {
                        float sx = fminf(fmaxf(((float)x - (float)x0 + 0.5f) * scx - 0.5f, 0.0f), 27.0f);
                        val = bilin_ref(lg, sx, sy);
                    }
                    unsigned int bits = __ballot_sync(0xffffffffu, inb && (val > 0.0f));
                    if (lane == 0) {
                        if (dst) dst[xw - xw0] = bits;
                        lm += __popc(bits);
                    }
                }
            }
            if (lane == 0 && lm) atomicAdd(&s_cnt, lm);
        }
        __syncthreads();
        if (t == 0) {
            g_msumP[i][slice] = s_cnt;
            __threadfence();
            atomicAdd(&g_rdone[i], 1);
        }
        return;
    }

    // ============================= SCAN CTAs =================================
    int c = bid - SBASE;
    unsigned int* cm = &g_cmask[c][0];

    if (t < N) sp[t] = prob[t];
    __syncthreads();
    if (t < N) {
        float pi = sp[t];
        int r = 0;
        for (int j = 0; j < N; j++) {
            float pj = sp[j];
            r += (pj > pi) || (pj == pi && j < t);
        }
        sord[r] = t;
        scls[r] = clsidx[t] - 1;
    }
    __syncthreads();

    if (t == 0) {
        int k = 0;
        for (int i = 0; i < N; i++)
            if (scls[i] == c) s_list[k++] = i;
        s_k = k;
    }
    __syncthreads();
    int k = s_k;

    if (k > 0) {
        if (t < k) {
            int i = s_list[t];
            while (atomicAdd(&g_rdone[i], 0) < NSPLIT) __nanosleep(64);
        }
        __syncthreads();
        __threadfence();

        if (k == 1) {
            if (t == 0) {
                int i = s_list[0];
                int msum = 0;
                #pragma unroll
                for (int u = 0; u < NSPLIT; u++) msum += g_msumP[i][u];
                g_keep[i] = (msum > 0);
            }
        } else {
            int kc = min(k, 16);
            if (t < kc) {
                int i = s_list[t];
                float4 rb = reinterpret_cast<const float4*>(rois)[sord[i]];
                s_gx0[t] = max((int)rb.x, 0);
                s_gx1[t] = min((int)rb.z + 1, IMG_W);
                s_gy0[t] = max((int)rb.y, 0);
                s_gy1[t] = min((int)rb.w + 1, IMG_H);
            }
            __syncthreads();
            if (t == 0) {
                int ux0 = IMG_W, ux1 = 0, uy0 = IMG_H, uy1 = 0;
                for (int j = 0; j < kc; j++) {
                    if (s_gx0[j] < s_gx1[j] && s_gy0[j] < s_gy1[j]) {
                        ux0 = min(ux0, s_gx0[j]); ux1 = max(ux1, s_gx1[j]);
                        uy0 = min(uy0, s_gy0[j]); uy1 = max(uy1, s_gy1[j]);
                    }
                }
                if (k > 16) { ux0 = 0; ux1 = IMG_W; uy0 = 0; uy1 = IMG_H; }
                s_ext[0] = ux0 >> 5;
                s_ext[1] = (ux1 + 31) >> 5;
                s_ext[2] = uy0;
                s_ext[3] = uy1;
            }
            __syncthreads();
            int uw0 = s_ext[0], uw1 = s_ext[1], uy0 = s_ext[2], uy1 = s_ext[3];
            int unw = max(uw1 - uw0, 0);
            int unrows = max(uy1 - uy0, 0);
            for (int w = t; w < unw * unrows; w += blockDim.x) {
                int r = w / unw;
                cm[(uy0 + r) * WPR + uw0 + (w - r * unw)] = 0u;
            }
            __syncthreads();

            bool mask_ne = false;

            for (int j = 0; j < k; j++) {
                int i = s_list[j];
                int msum = 0;
                #pragma unroll
                for (int u = 0; u < NSPLIT; u++) msum += g_msumP[i][u];
                if (msum == 0) { if (t == 0) g_keep[i] = 0; continue; }

                int xs0, xs1, ys0, ys1;
                if (j < 16) {
                    xs0 = s_gx0[j]; xs1 = s_gx1[j]; ys0 = s_gy0[j]; ys1 = s_gy1[j];
                } else {
                    float4 rb = reinterpret_cast<const float4*>(rois)[sord[i]];
                    xs0 = max((int)rb.x, 0); xs1 = min((int)rb.z + 1, IMG_W);
                    ys0 = max((int)rb.y, 0); ys1 = min((int)rb.w + 1, IMG_H);
                }
                int bh = ys1 - ys0;
                int xw0 = xs0 >> 5, xw1 = (xs1 + 31) >> 5;
                int nwx = xw1 - xw0;
                int total = nwx * bh;
                bool fits = (total <= BITSW);

                if (t == 0) s_ovl = 0;
                __syncthreads();

                if (mask_ne) {
                    int lo = 0;
                    if (fits) {
                        const unsigned int* bi = g_bits[i];
                        for (int kk = t; kk < total; kk += blockDim.x) {
                            unsigned int b = bi[kk];
                            if (b) {
                                int ry = kk / nwx;
                                int xw = xw0 + (kk - ry * nwx);
                                lo += __popc(b & cm[(ys0 + ry) * WPR + xw]);
                            }
                        }
                    } else {
                        int o = sord[i];
                        const float* lp = mask_prob + (long long)o * (MM * MM);
                        for (int u = t; u < MM * MM; u += blockDim.x) lg[u] = lp[u];
                        __syncthreads();
                        float4 rb = reinterpret_cast<const float4*>(rois)[o];
                        int x0 = (int)rb.x, y0 = (int)rb.y, x1 = (int)rb.z, y1 = (int)rb.w;
                        float wv = fmaxf((float)(x1 - x0 + 1), 1.0f);
                        float hv = fmaxf((float)(y1 - y0 + 1), 1.0f);
                        float scx = 28.0f / wv, scy = 28.0f / hv;
                        for (int kk = t; kk < total; kk += blockDim.x) {
                            int ry = kk / nwx;
                            int yy = ys0 + ry;
                            int xw = xw0 + (kk - ry * nwx);
                            unsigned int cw = cm[yy * WPR + xw];
                            if (!cw) continue;
                            float sy = fminf(fmaxf(((float)yy - (float)y0 + 0.5f) * scy - 0.5f, 0.0f), 27.0f);
                            int xlo2 = max(xs0, xw << 5);
                            int xhi2 = min(xs1, (xw << 5) + 32);
                            for (int x = xlo2; x < xhi2; x++) {
                                if (cw & (1u << (x & 31))) {
                                    float sx = fminf(fmaxf(((float)x - (float)x0 + 0.5f) * scx - 0.5f, 0.0f), 27.0f);
                                    if (bilin_ref(lg, sx, sy) > 0.0f) lo++;
                                }
                            }
                        }
                    }
                    #pragma unroll
                    for (int off = 16; off > 0; off >>= 1)
                        lo += __shfl_down_sync(0xffffffffu, lo, off);
                    if ((t & 31) == 0 && lo) atomicAdd(&s_ovl, lo);
                }
                __syncthreads();

                if (t == 0) {
                    int kp = ((float)s_ovl <= 0.3f * (float)msum);
                    s_keep = kp;
                    g_keep[i] = kp;
                }
                __syncthreads();

                if (s_keep && j < k - 1) {
                    if (fits) {
                        const unsigned int* bi = g_bits[i];
                        for (int kk = t; kk < total; kk += blockDim.x) {
                            unsigned int b = bi[kk];
                            if (b) {
                                int ry = kk / nwx;
                                int xw = xw0 + (kk - ry * nwx);
                                cm[(ys0 + ry) * WPR + xw] |= b;
                            }
                        }
                    } else {
                        int o = sord[i];
                        const float* lp = mask_prob + (long long)o * (MM * MM);
                        for (int u = t; u < MM * MM; u += blockDim.x) lg[u] = lp[u];
                        __syncthreads();
                        float4 rb = reinterpret_cast<const float4*>(rois)[o];
                        int x0 = (int)rb.x, y0 = (int)rb.y, x1 = (int)rb.z, y1 = (int)rb.w;
                        float wv = fmaxf((float)(x1 - x0 + 1), 1.0f);
                        float hv = fmaxf((float)(y1 - y0 + 1), 1.0f);
                        float scx = 28.0f / wv, scy = 28.0f / hv;
                        for (int kk = t; kk < total; kk += blockDim.x) {
                            int ry = kk / nwx;
                            int yy = ys0 + ry;
                            int xw = xw0 + (kk - ry * nwx);
                            float sy = fminf(fmaxf(((float)yy - (float)y0 + 0.5f) * scy - 0.5f, 0.0f), 27.0f);
                            int xlo2 = max(xs0, xw << 5);
                            int xhi2 = min(xs1, (xw << 5) + 32);
                            unsigned int bits = 0u;
                            for (int x = xlo2; x < xhi2; x++) {
                                float sx = fminf(fmaxf(((float)x - (float)x0 + 0.5f) * scx - 0.5f, 0.0f), 27.0f);
                                if (bilin_ref(lg, sx, sy) > 0.0f) bits |= (1u << (x & 31));
                            }
                            if (bits) cm[yy * WPR + xw] |= bits;
                        }
                    }
                    mask_ne = true;
                }
                __syncthreads();
            }
        }
    }

    // ---- scan ticket; last CTA compacts, resets counters, raises g_sdone ---
    __syncthreads();
    if (t == 0) {
        __threadfence();
        s_ticket = atomicAdd(&g_done, 1);
    }
    __syncthreads();
    if (s_ticket != NCLS - 1) return;

    __threadfence();
    int kv = (t < N) ? g_keep[t] : 0;
    if (t < MAXN) pf[t] = kv;
    __syncthreads();
    #pragma unroll
    for (int off = 1; off < MAXN; off <<= 1) {
        int v = (t < MAXN && t >= off) ? pf[t - off] : 0;
        __syncthreads();
        if (t < MAXN) pf[t] += v;
        __syncthreads();
    }
    int nk = pf[N - 1];
    if (t < N) {
        if (kv) {
            g_po[pf[t] - 1] = sord[t];
            if (has_keep) out_keep[pf[t] - 1] = (float)sord[t];
        }
        if (has_keep && t >= nk) out_keep[t] = -1.0f;
    }
    if (t < N) {
        while (atomicAdd(&g_rdone[t], 0) < NSPLIT) __nanosleep(64);
    }
    __syncthreads();
    if (t < MAXN) g_rdone[t] = 0;
    if (t == 0) {
        g_nk = nk;
        g_done = 0;
        __threadfence();
        atomicExch(&g_sdone, 1);               // release the writers
    }
}

// ---------------------------------------------------------------------------
extern "C" void kernel_launch(void* const* d_in, const int* in_sizes, int n_in,
                              void* d_out, int out_size) {
    const float* rois  = (const float*)d_in[0];
    const float* prob  = (const float*)d_in[1];
    const float* mp    = (const float*)d_in[2];
    const int*   cidx  = (const int*)d_in[3];

    int N = in_sizes[1];
    if (N > MAXN) N = MAXN;

    float* out = (float*)d_out;
    long long HW = (long long)IMG_H * IMG_W;
    int has_keep = ((long long)out_size == (long long)N + (long long)N * HW) ? 1 : 0;
    float* energy = out + (has_keep ? N : 0);

    int grid = N * NSPLIT + NCLS + N * WPS;
    k_all<<<grid, 256>>>(rois, prob, cidx, mp, out, (float4*)energy, N, has_keep);
}

// round 17
// speedup vs baseline: 1.0998x; 1.0998x over previous
#include <cuda_runtime.h>

// ---------------------------------------------------------------------------
// MaskRemoval — R17: R14 overlap + per-slot zero gating for in-kernel paste.
//   grid (1D), dispatch order:
//     [0, NCLS)            scan CTAs (spin on raster counters; last ticket
//                          compacts -> g_po/g_nk/keep_inds, resets raster
//                          counters, raises g_sdone)
//     [NCLS, +N*YDIM)      y%3<2: zero-writer of a CONTIGUOUS (slot, 1/16)
//                          chunk -> g_zslot[slot]++ when done.
//                          y%3==2: raster slice -> g_bits+g_msumP+g_rdone++
//     tail: N*PSPLIT       paste CTAs: spin on g_sdone && g_zslot[slot]==16,
//                          then bilinear-paste their (slot, y-slice).
//                          Last paste ticket resets flags for graph replay.
// ---------------------------------------------------------------------------

#define MAXN   128
#define NCLS   80
#define MM     28
#define IMG_H  800
#define IMG_W  800
#define WPR    25
#define BOXMAX 384
#define NSPLIT 8                       // raster y-slices per ROI
#define PSPLIT 8                       // paste y-slices per slot
#define ZSPLIT 16                      // zero chunks per slot
#define YDIM   (ZSPLIT + NSPLIT)       // 24
#define BITSW  8192
#define HW     (IMG_H * IMG_W)
#define CH4    (HW / 4 / ZSPLIT)       // 10000 float4 per zero chunk

__device__ int g_keep[MAXN];
__device__ int g_msumP[MAXN][NSPLIT];
__device__ unsigned int g_bits[MAXN][BITSW];
__device__ unsigned int g_cmask[NCLS][IMG_H * WPR];
__device__ int g_rdone[MAXN];          // per-ROI raster completion
__device__ int g_zslot[MAXN];          // per-slot zero-chunk completion
__device__ int g_done  = 0;            // scan ticket
__device__ int g_sdone = 0;            // scan+compaction complete
__device__ int g_pdone = 0;            // paste ticket
__device__ int g_po[MAXN];
__device__ int g_nk;

__device__ __forceinline__ float bilin_ref(const float* lg, float sx, float sy) {
    int ix0 = (int)sx;
    int iy0 = (int)sy;
    int ix1 = min(ix0 + 1, MM - 1);
    int iy1 = min(iy0 + 1, MM - 1);
    float fx = sx - (float)ix0;
    float fy = sy - (float)iy0;
    float v00 = lg[iy0 * MM + ix0], v01 = lg[iy0 * MM + ix1];
    float v10 = lg[iy1 * MM + ix0], v11 = lg[iy1 * MM + ix1];
    return (1.0f - fy) * ((1.0f - fx) * v00 + fx * v01)
         +         fy  * ((1.0f - fx) * v10 + fx * v11);
}

// ---------------------------------------------------------------------------
__global__ __launch_bounds__(256) void k_all(const float* __restrict__ rois,
                                             const float* __restrict__ prob,
                                             const int*   __restrict__ clsidx,
                                             const float* __restrict__ mask_prob,
                                             float* __restrict__ out_keep,
                                             float4* __restrict__ energy4,
                                             float* __restrict__ energy,
                                             int N, int has_keep) {
    __shared__ float sp[MAXN];
    __shared__ int   sord[MAXN];
    __shared__ int   scls[MAXN];
    __shared__ int   s_list[MAXN];
    __shared__ int   pf[MAXN];
    __shared__ int   s_k, s_ticket;
    __shared__ int   s_gx0[16], s_gx1[16], s_gy0[16], s_gy1[16];
    __shared__ int   s_ext[4];
    __shared__ int   s_ovl, s_keep, s_cnt;
    __shared__ float lg[MM * MM];
    __shared__ float2 s_cx[BOXMAX];

    int t = threadIdx.x;
    int warpi = t >> 5;
    int lane  = t & 31;
    int nwarps = blockDim.x >> 5;
    int bid = blockIdx.x;
    const int PBASE = NCLS + N * YDIM;

    // ============================ PASTE CTAs (tail) ==========================
    if (bid >= PBASE) {
        int pid = bid - PBASE;
        int slice = pid / N;
        int slot  = pid - slice * N;

        if (t == 0) {
            while (atomicAdd(&g_sdone, 0) == 0) __nanosleep(128);
            while (atomicAdd(&g_zslot[slot], 0) < ZSPLIT) __nanosleep(128);
        }
        __syncthreads();
        __threadfence();

        if (slot < g_nk) {
            int o = g_po[slot];
            float4 rb = reinterpret_cast<const float4*>(rois)[o];
            int x0 = (int)rb.x, y0 = (int)rb.y, x1 = (int)rb.z, y1 = (int)rb.w;
            int xs0 = max(x0, 0), xs1 = min(x1 + 1, IMG_W);
            int ys0 = max(y0, 0), ys1 = min(y1 + 1, IMG_H);
            int bw = xs1 - xs0, bh = ys1 - ys0;
            if (bw > 0 && bh > 0) {
                const float* lp = mask_prob + (long long)o * (MM * MM);
                for (int u = t; u < MM * MM; u += blockDim.x) lg[u] = lp[u];
                float wv = fmaxf((float)(x1 - x0 + 1), 1.0f);
                float hv = fmaxf((float)(y1 - y0 + 1), 1.0f);
                float scx = 28.0f / wv, scy = 28.0f / hv;
                bool pre = (bw <= BOXMAX);
                if (pre) {
                    for (int u = t; u < bw; u += blockDim.x) {
                        float sx = fminf(fmaxf(((float)(xs0 + u) - (float)x0 + 0.5f) * scx - 0.5f, 0.0f), 27.0f);
                        int ix0 = (int)sx;
                        s_cx[u] = make_float2(sx - (float)ix0, __int_as_float(ix0));
                    }
                }
                __syncthreads();

                int chunk = (bh + PSPLIT - 1) / PSPLIT;
                int ry0   = slice * chunk;
                int rows  = min(chunk, bh - ry0);
                if (rows > 0) {
                    int xw0 = xs0 >> 5, xw1 = (xs1 + 31) >> 5;
                    float* base = energy + (long long)slot * HW;
                    for (int r = warpi; r < rows; r += nwarps) {
                        int ry = ry0 + r;
                        int y  = ys0 + ry;
                        float sy = fminf(fmaxf(((float)y - (float)y0 + 0.5f) * scy - 0.5f, 0.0f), 27.0f);
                        int iy0 = (int)sy;
                        int iy1 = min(iy0 + 1, MM - 1);
                        float fy = sy - (float)iy0;
                        int ll = min(lane, MM - 1);
                        float r0v = lg[iy0 * MM + ll];
                        float r1v = lg[iy1 * MM + ll];
                        float* rowp = base + y * IMG_W;
                        for (int xw = xw0; xw < xw1; xw++) {
                            int x = (xw << 5) + lane;
                            bool inb = (x >= xs0) && (x < xs1);
                            float val;
                            if (pre) {
                                float2 cf = s_cx[inb ? (x - xs0) : 0];
                                float fx = cf.x;
                                int ix0 = __float_as_int(cf.y);
                                int ix1 = min(ix0 + 1, MM - 1);
                                float v00 = __shfl_sync(0xffffffffu, r0v, ix0);
                                float v01 = __shfl_sync(0xffffffffu, r0v, ix1);
                                float v10 = __shfl_sync(0xffffffffu, r1v, ix0);
                                float v11 = __shfl_sync(0xffffffffu, r1v, ix1);
                                val = (1.0f - fy) * ((1.0f - fx) * v00 + fx * v01)
                                    +         fy  * ((1.0f - fx) * v10 + fx * v11);
                            } else {
                                float sx = fminf(fmaxf(((float)x - (float)x0 + 0.5f) * scx - 0.5f, 0.0f), 27.0f);
                                val = bilin_ref(lg, sx, sy);
                            }
                            if (inb) rowp[x] = val;
                        }
                    }
                }
            }
        }
        __syncthreads();
        if (t == 0) {
            int tk = atomicAdd(&g_pdone, 1);
            if (tk == N * PSPLIT - 1) {          // last paste: reset replay flags
                for (int u = 0; u < MAXN; u++) g_zslot[u] = 0;
                g_sdone = 0;
                g_pdone = 0;
                __threadfence();
            }
        }
        return;
    }

    // ======================= writer / raster CTAs ===========================
    if (bid >= NCLS) {
        int rest = bid - NCLS;
        int y = rest / N;
        int i = rest - y * N;
        int ymod = y % 3;

        if (ymod != 2) {
            // ---- zero-writer: contiguous chunk (slot=i, part=widx) ----------
            int widx = (y / 3) * 2 + ymod;       // 0..15
            float4* base = energy4 + (long long)i * (HW / 4) + (long long)widx * CH4;
            float4 z = make_float4(0.f, 0.f, 0.f, 0.f);
            int idx = t;
            #pragma unroll 1
            for (; idx + 3 * 256 < CH4; idx += 4 * 256) {
                __stcs(&base[idx], z);
                __stcs(&base[idx + 256], z);
                __stcs(&base[idx + 512], z);
                __stcs(&base[idx + 768], z);
            }
            for (; idx < CH4; idx += 256) __stcs(&base[idx], z);
            __syncthreads();
            if (t == 0) {
                __threadfence();
                atomicAdd(&g_zslot[i], 1);
            }
            return;
        }

        // ---- raster slice ------------------------------------------------------
        int slice = y / 3;
        if (t < N) sp[t] = prob[t];
        __syncthreads();
        if (t < N) {
            float pi = sp[t];
            int r = 0;
            for (int j = 0; j < N; j++) {
                float pj = sp[j];
                r += (pj > pi) || (pj == pi && j < t);
            }
            sord[r] = t;
        }
        if (t == 0) s_cnt = 0;
        __syncthreads();

        int o = sord[i];
        float4 rb = reinterpret_cast<const float4*>(rois)[o];
        int x0 = (int)rb.x, y0 = (int)rb.y, x1 = (int)rb.z, y1 = (int)rb.w;
        int xs0 = max(x0, 0), xs1 = min(x1 + 1, IMG_W);
        int ys0 = max(y0, 0), ys1 = min(y1 + 1, IMG_H);
        int bw = xs1 - xs0, bh = ys1 - ys0;
        bool active = (bw > 0) && (bh > 0);

        float wv = fmaxf((float)(x1 - x0 + 1), 1.0f);
        float hv = fmaxf((float)(y1 - y0 + 1), 1.0f);
        float scx = 28.0f / wv, scy = 28.0f / hv;
        bool pre = active && (bw <= BOXMAX);
        int rows = 0, ry0 = 0;

        if (active) {
            const float* lp = mask_prob + (long long)o * (MM * MM);
            for (int u = t; u < MM * MM; u += blockDim.x) lg[u] = lp[u];
            if (pre) {
                for (int u = t; u < bw; u += blockDim.x) {
                    float sx = fminf(fmaxf(((float)(xs0 + u) - (float)x0 + 0.5f) * scx - 0.5f, 0.0f), 27.0f);
                    int ix0 = (int)sx;
                    s_cx[u] = make_float2(sx - (float)ix0, __int_as_float(ix0));
                }
            }
            int chunk = (bh + NSPLIT - 1) / NSPLIT;
            ry0  = slice * chunk;
            rows = min(chunk, bh - ry0);
        }
        __syncthreads();

        if (active && rows > 0) {
            int xw0 = xs0 >> 5, xw1 = (xs1 + 31) >> 5;
            int nwx = xw1 - xw0;
            bool fits = (nwx * bh <= BITSW);
            int lm = 0;
            for (int r = warpi; r < rows; r += nwarps) {
                int ry = ry0 + r;
                int yy = ys0 + ry;
                float sy = fminf(fmaxf(((float)yy - (float)y0 + 0.5f) * scy - 0.5f, 0.0f), 27.0f);
                int iy0 = (int)sy;
                int iy1 = min(iy0 + 1, MM - 1);
                float fy = sy - (float)iy0;
                int ll = min(lane, MM - 1);
                float r0v = lg[iy0 * MM + ll];
                float r1v = lg[iy1 * MM + ll];
                unsigned int* dst = fits ? &g_bits[i][ry * nwx] : nullptr;
                for (int xw = xw0; xw < xw1; xw++) {
                    int x = (xw << 5) + lane;
                    bool inb = (x >= xs0) && (x < xs1);
                    float val;
                    if (pre) {
                        float2 cf = s_cx[inb ? (x - xs0) : 0];
                        float fx = cf.x;
                        int ix0 = __float_as_int(cf.y);
                        int ix1 = min(ix0 + 1, MM - 1);
                        float v00 = __shfl_sync(0xffffffffu, r0v, ix0);
                        float v01 = __shfl_sync(0xffffffffu, r0v, ix1);
                        float v10 = __shfl_sync(0xffffffffu, r1v, ix0);
                        float v11 = __shfl_sync(0xffffffffu, r1v, ix1);
                        val = (1.0f - fy) * ((1.0f - fx) * v00 + fx * v01)
                            +         fy  * ((1.0f - fx) * v10 + fx * v11);
                    } else {
                        float sx = fminf(fmaxf(((float)x - (float)x0 + 0.5f) * scx - 0.5f, 0.0f), 27.0f);
                        val = bilin_ref(lg, sx, sy);
                    }
                    unsigned int bits = __ballot_sync(0xffffffffu, inb && (val > 0.0f));
                    if (lane == 0) {
                        if (dst) dst[xw - xw0] = bits;
                        lm += __popc(bits);
                    }
                }
            }
            if (lane == 0 && lm) atomicAdd(&s_cnt, lm);
        }
        __syncthreads();
        if (t == 0) {
            g_msumP[i][slice] = s_cnt;
            __threadfence();
            atomicAdd(&g_rdone[i], 1);
        }
        return;
    }

    // =========================== scan CTA (one class) =======================
    int c = bid;
    unsigned int* cm = &g_cmask[c][0];

    if (t < N) sp[t] = prob[t];
    __syncthreads();
    if (t < N) {
        float pi = sp[t];
        int r = 0;
        for (int j = 0; j < N; j++) {
            float pj = sp[j];
            r += (pj > pi) || (pj == pi && j < t);
        }
        sord[r] = t;
        scls[r] = clsidx[t] - 1;
    }
    __syncthreads();

    if (t == 0) {
        int k = 0;
        for (int i = 0; i < N; i++)
            if (scls[i] == c) s_list[k++] = i;
        s_k = k;
    }
    __syncthreads();
    int k = s_k;

    if (k > 0) {
        if (t < k) {
            int i = s_list[t];
            while (atomicAdd(&g_rdone[i], 0) < NSPLIT) __nanosleep(64);
        }
        __syncthreads();
        __threadfence();

        if (k == 1) {
            if (t == 0) {
                int i = s_list[0];
                int msum = 0;
                #pragma unroll
                for (int u = 0; u < NSPLIT; u++) msum += g_msumP[i][u];
                g_keep[i] = (msum > 0);
            }
        } else {
            int kc = min(k, 16);
            if (t < kc) {
                int i = s_list[t];
                float4 rb = reinterpret_cast<const float4*>(rois)[sord[i]];
                s_gx0[t] = max((int)rb.x, 0);
                s_gx1[t] = min((int)rb.z + 1, IMG_W);
                s_gy0[t] = max((int)rb.y, 0);
                s_gy1[t] = min((int)rb.w + 1, IMG_H);
            }
            __syncthreads();
            if (t == 0) {
                int ux0 = IMG_W, ux1 = 0, uy0 = IMG_H, uy1 = 0;
                for (int j = 0; j < kc; j++) {
                    if (s_gx0[j] < s_gx1[j] && s_gy0[j] < s_gy1[j]) {
                        ux0 = min(ux0, s_gx0[j]); ux1 = max(ux1, s_gx1[j]);
                        uy0 = min(uy0, s_gy0[j]); uy1 = max(uy1, s_gy1[j]);
                    }
                }
                if (k > 16) { ux0 = 0; ux1 = IMG_W; uy0 = 0; uy1 = IMG_H; }
                s_ext[0] = ux0 >> 5;
                s_ext[1] = (ux1 + 31) >> 5;
                s_ext[2] = uy0;
                s_ext[3] = uy1;
            }
            __syncthreads();
            int uw0 = s_ext[0], uw1 = s_ext[1], uy0 = s_ext[2], uy1 = s_ext[3];
            int unw = max(uw1 - uw0, 0);
            int unrows = max(uy1 - uy0, 0);
            for (int w = t; w < unw * unrows; w += blockDim.x) {
                int r = w / unw;
                cm[(uy0 + r) * WPR + uw0 + (w - r * unw)] = 0u;
            }
            __syncthreads();

            bool mask_ne = false;

            for (int j = 0; j < k; j++) {
                int i = s_list[j];
                int msum = 0;
                #pragma unroll
                for (int u = 0; u < NSPLIT; u++) msum += g_msumP[i][u];
                if (msum == 0) { if (t == 0) g_keep[i] = 0; continue; }

                int xs0, xs1, ys0, ys1;
                if (j < 16) {
                    xs0 = s_gx0[j]; xs1 = s_gx1[j]; ys0 = s_gy0[j]; ys1 = s_gy1[j];
                } else {
                    float4 rb = reinterpret_cast<const float4*>(rois)[sord[i]];
                    xs0 = max((int)rb.x, 0); xs1 = min((int)rb.z + 1, IMG_W);
                    ys0 = max((int)rb.y, 0); ys1 = min((int)rb.w + 1, IMG_H);
                }
                int bh = ys1 - ys0;
                int xw0 = xs0 >> 5, xw1 = (xs1 + 31) >> 5;
                int nwx = xw1 - xw0;
                int total = nwx * bh;
                bool fits = (total <= BITSW);

                if (t == 0) s_ovl = 0;
                __syncthreads();

                if (mask_ne) {
                    int lo = 0;
                    if (fits) {
                        const unsigned int* bi = g_bits[i];
                        for (int kk = t; kk < total; kk += blockDim.x) {
                            unsigned int b = bi[kk];
                            if (b) {
                                int ry = kk / nwx;
                                int xw = xw0 + (kk - ry * nwx);
                                lo += __popc(b & cm[(ys0 + ry) * WPR + xw]);
                            }
                        }
                    } else {
                        int o = sord[i];
                        const float* lp = mask_prob + (long long)o * (MM * MM);
                        for (int u = t; u < MM * MM; u += blockDim.x) lg[u] = lp[u];
                        __syncthreads();
                        float4 rb = reinterpret_cast<const float4*>(rois)[o];
                        int x0 = (int)rb.x, y0 = (int)rb.y, x1 = (int)rb.z, y1 = (int)rb.w;
                        float wv = fmaxf((float)(x1 - x0 + 1), 1.0f);
                        float hv = fmaxf((float)(y1 - y0 + 1), 1.0f);
                        float scx = 28.0f / wv, scy = 28.0f / hv;
                        for (int kk = t; kk < total; kk += blockDim.x) {
                            int ry = kk / nwx;
                            int yy = ys0 + ry;
                            int xw = xw0 + (kk - ry * nwx);
                            unsigned int cw = cm[yy * WPR + xw];
                            if (!cw) continue;
                            float sy = fminf(fmaxf(((float)yy - (float)y0 + 0.5f) * scy - 0.5f, 0.0f), 27.0f);
                            int xlo2 = max(xs0, xw << 5);
                            int xhi2 = min(xs1, (xw << 5) + 32);
                            for (int x = xlo2; x < xhi2; x++) {
                                if (cw & (1u << (x & 31))) {
                                    float sx = fminf(fmaxf(((float)x - (float)x0 + 0.5f) * scx - 0.5f, 0.0f), 27.0f);
                                    if (bilin_ref(lg, sx, sy) > 0.0f) lo++;
                                }
                            }
                        }
                    }
                    #pragma unroll
                    for (int off = 16; off > 0; off >>= 1)
                        lo += __shfl_down_sync(0xffffffffu, lo, off);
                    if ((t & 31) == 0 && lo) atomicAdd(&s_ovl, lo);
                }
                __syncthreads();

                if (t == 0) {
                    int kp = ((float)s_ovl <= 0.3f * (float)msum);
                    s_keep = kp;
                    g_keep[i] = kp;
                }
                __syncthreads();

                if (s_keep && j < k - 1) {
                    if (fits) {
                        const unsigned int* bi = g_bits[i];
                        for (int kk = t; kk < total; kk += blockDim.x) {
                            unsigned int b = bi[kk];
                            if (b) {
                                int ry = kk / nwx;
                                int xw = xw0 + (kk - ry * nwx);
                                cm[(ys0 + ry) * WPR + xw] |= b;
                            }
                        }
                    } else {
                        int o = sord[i];
                        const float* lp = mask_prob + (long long)o * (MM * MM);
                        for (int u = t; u < MM * MM; u += blockDim.x) lg[u] = lp[u];
                        __syncthreads();
                        float4 rb = reinterpret_cast<const float4*>(rois)[o];
                        int x0 = (int)rb.x, y0 = (int)rb.y, x1 = (int)rb.z, y1 = (int)rb.w;
                        float wv = fmaxf((float)(x1 - x0 + 1), 1.0f);
                        float hv = fmaxf((float)(y1 - y0 + 1), 1.0f);
                        float scx = 28.0f / wv, scy = 28.0f / hv;
                        for (int kk = t; kk < total; kk += blockDim.x) {
                            int ry = kk / nwx;
                            int yy = ys0 + ry;
                            int xw = xw0 + (kk - ry * nwx);
                            float sy = fminf(fmaxf(((float)yy - (float)y0 + 0.5f) * scy - 0.5f, 0.0f), 27.0f);
                            int xlo2 = max(xs0, xw << 5);
                            int xhi2 = min(xs1, (xw << 5) + 32);
                            unsigned int bits = 0u;
                            for (int x = xlo2; x < xhi2; x++) {
                                float sx = fminf(fmaxf(((float)x - (float)x0 + 0.5f) * scx - 0.5f, 0.0f), 27.0f);
                                if (bilin_ref(lg, sx, sy) > 0.0f) bits |= (1u << (x & 31));
                            }
                            if (bits) cm[yy * WPR + xw] |= bits;
                        }
                    }
                    mask_ne = true;
                }
                __syncthreads();
            }
        }
    }

    // ---- scan ticket; last CTA compacts + raises g_sdone --------------------
    __syncthreads();
    if (t == 0) {
        __threadfence();
        s_ticket = atomicAdd(&g_done, 1);
    }
    __syncthreads();
    if (s_ticket != NCLS - 1) return;

    __threadfence();
    int kv = (t < N) ? g_keep[t] : 0;
    if (t < MAXN) pf[t] = kv;
    __syncthreads();
    #pragma unroll
    for (int off = 1; off < MAXN; off <<= 1) {
        int v = (t < MAXN && t >= off) ? pf[t - off] : 0;
        __syncthreads();
        if (t < MAXN) pf[t] += v;
        __syncthreads();
    }
    int nk = pf[N - 1];
    if (t < N) {
        if (kv) {
            g_po[pf[t] - 1] = sord[t];
            if (has_keep) out_keep[pf[t] - 1] = (float)sord[t];
        }
        if (has_keep && t >= nk) out_keep[t] = -1.0f;
    }
    if (t < N) {
        while (atomicAdd(&g_rdone[t], 0) < NSPLIT) __nanosleep(64);
    }
    __syncthreads();
    if (t < MAXN) g_rdone[t] = 0;
    if (t == 0) {
        g_nk = nk;
        g_done = 0;
        __threadfence();
        atomicExch(&g_sdone, 1);
    }
}

// ---------------------------------------------------------------------------
extern "C" void kernel_launch(void* const* d_in, const int* in_sizes, int n_in,
                              void* d_out, int out_size) {
    const float* rois  = (const float*)d_in[0];
    const float* prob  = (const float*)d_in[1];
    const float* mp    = (const float*)d_in[2];
    const int*   cidx  = (const int*)d_in[3];

    int N = in_sizes[1];
    if (N > MAXN) N = MAXN;

    float* out = (float*)d_out;
    long long HWll = (long long)IMG_H * IMG_W;
    int has_keep = ((long long)out_size == (long long)N + (long long)N * HWll) ? 1 : 0;
    float* energy = out + (has_keep ? N : 0);

    int grid = NCLS + N * YDIM + N * PSPLIT;
    k_all<<<grid, 256>>>(rois, prob, cidx, mp, out,
                         (float4*)energy, energy, N, has_keep);
}